// round 15
// baseline (speedup 1.0000x reference)
#include <cuda_runtime.h>
#include <cuda_fp16.h>

#define DT 0.01f

// Fixed problem shape: B=2, N=20000, D=64, E=320000
#define MAX_B 2
#define MAX_N 20000
#define MAX_D 64

// S_h[b][n][d] (fp16) = sum over edges with dst==n of fp16(q[b][src][d]).
// Zero at module load; final_kernel self-cleans after consuming.
static __device__ __half g_Sh[MAX_B * MAX_N * MAX_D];
// fp16 copy of q, rebuilt from the input on EVERY launch (no caching):
// halves the edge kernel's gather bytes.
static __device__ __half g_qh[MAX_B * MAX_N * MAX_D];
static __device__ int    g_deg[2 * MAX_N];   // per-batch replicated degree

__device__ __forceinline__ void red_add_v4_f16x2(__half* addr,
                                                 unsigned a, unsigned b,
                                                 unsigned c, unsigned d) {
    asm volatile("red.global.add.noftz.v4.f16x2 [%0], {%1,%2,%3,%4};"
                 :: "l"(addr), "r"(a), "r"(b), "r"(c), "r"(d)
                 : "memory");
}

__device__ __forceinline__ void red_add_s32(int* addr, int v) {
    asm volatile("red.global.add.s32 [%0], %1;"
                 :: "l"(addr), "r"(v)
                 : "memory");
}

__device__ __forceinline__ unsigned pack_h2(float x, float y) {
    __half2 h = __floats2half2_rn(x, y);
    return *reinterpret_cast<unsigned*>(&h);
}

// ---------------------------------------------------------------------------
// Kernel 0: q (fp32) -> g_qh (fp16). ONE FLOAT4 PER THREAD (640K threads,
// 2500 blocks): R12/R13 ncu shows these short streaming kernels are
// latency-bound and scale with thread count, not per-thread ILP.
// total4 = B*N*D/4 = 640000 = 2500 x 256.
// ---------------------------------------------------------------------------
__global__ void convert_kernel(const float* __restrict__ q, int total4) {
    int i = blockIdx.x * blockDim.x + threadIdx.x;
    if (i >= total4) return;
    float4 a = __ldg(reinterpret_cast<const float4*>(q) + i);
    uint2 h;
    h.x = pack_h2(a.x, a.y);
    h.y = pack_h2(a.z, a.w);
    reinterpret_cast<uint2*>(g_qh)[i] = h;
}

// ---------------------------------------------------------------------------
// Kernel 1: edge scatter, all-fp16. 8 lanes per edge; lane c covers elems
// [8c,8c+8). Per lane per batch: 1x LDG.128 of 8 fp16 + 1x RED.128 f16x2.
// Grid exact: E*8 = 2,560,000 = 10,000 x 256.
// ---------------------------------------------------------------------------
__global__ void edge_kernel(const int* __restrict__ edges, int E, int N) {
    int tid = blockIdx.x * blockDim.x + threadIdx.x;
    int e = tid >> 3;
    int c = tid & 7;
    if (e >= E) return;

    int2 ed = __ldg(reinterpret_cast<const int2*>(edges) + e);
    int src = ed.x;
    int dst = ed.y;

    if (c < 2) red_add_s32(&g_deg[c * N + dst], 1);

    const uint4* qh16 = reinterpret_cast<const uint4*>(g_qh);
    // node row = 64 halfs = 128B = 8 uint4s
    uint4 v0 = __ldg(qh16 + src * 8 + c);            // batch 0
    uint4 v1 = __ldg(qh16 + (N + src) * 8 + c);      // batch 1

    red_add_v4_f16x2(&g_Sh[dst * 64 + c * 8],       v0.x, v0.y, v0.z, v0.w);
    red_add_v4_f16x2(&g_Sh[(N + dst) * 64 + c * 8], v1.x, v1.y, v1.z, v1.w);
}

// ---------------------------------------------------------------------------
// Kernel 2: fused leapfrog + Kalman epilogue, 4 elems/thread (640K threads).
// SELF-CLEANING: zeroes g_Sh / g_deg after consuming.
//   msg = deg*q - S ; ph = p + .5*DT*msg ; qn = q + DT*ph ; pn = p + DT*msg
//   n==0: inn = obs - qn; qn += kq*inn; pn += kp*inn
// Output: [q_new | p_new]. total4 = B*N*D/4 = 640000 = 2500 x 256.
// ---------------------------------------------------------------------------
__global__ void final_kernel(const float* __restrict__ q,
                             const float* __restrict__ p,
                             const float* __restrict__ obs,
                             const float* __restrict__ kg,
                             float* __restrict__ out,
                             int N, int total4) {
    int t = blockIdx.x * blockDim.x + threadIdx.x;
    if (t >= total4) return;

    int nodeIdx = t >> 4;                // b*N + n  (0 .. 2N-1)
    int c = t & 15;                      // float4 chunk within node

    const float4* q4 = reinterpret_cast<const float4*>(q);
    const float4* p4 = reinterpret_cast<const float4*>(p);

    float4 qv = __ldg(q4 + t);
    float4 pv = __ldg(p4 + t);
    uint2  sh = *reinterpret_cast<uint2*>(&g_Sh[t * 4]);
    float degf = (float)g_deg[nodeIdx];

    float2 f0 = __half22float2(*reinterpret_cast<__half2*>(&sh.x));
    float2 f1 = __half22float2(*reinterpret_cast<__half2*>(&sh.y));
    float sv[4] = {f0.x, f0.y, f1.x, f1.y};
    float qa[4] = {qv.x, qv.y, qv.z, qv.w};
    float pa[4] = {pv.x, pv.y, pv.z, pv.w};
    float qn[4], pn[4];

#pragma unroll
    for (int j = 0; j < 4; j++) {
        float msg = degf * qa[j] - sv[j];
        float ph  = pa[j] + 0.5f * DT * msg;
        qn[j] = qa[j] + DT * ph;
        pn[j] = ph + 0.5f * DT * msg;
    }

    if (nodeIdx == 0 || nodeIdx == N) {          // n == 0, batch 0 / 1
        int b = (nodeIdx == N) ? 1 : 0;
#pragma unroll
        for (int j = 0; j < 4; j++) {
            int d = c * 4 + j;
            float inn = __ldg(obs + b * 64 + d) - qn[j];
            qn[j] += __ldg(kg + d) * inn;
            pn[j] += __ldg(kg + 64 + d) * inn;
        }
    }

    float4* out4 = reinterpret_cast<float4*>(out);
    out4[t] = make_float4(qn[0], qn[1], qn[2], qn[3]);
    out4[total4 + t] = make_float4(pn[0], pn[1], pn[2], pn[3]);

    // ---- self-clean scratch for next replay ----
    *reinterpret_cast<uint2*>(&g_Sh[t * 4]) = make_uint2(0, 0);
    // deg read by this node's 16 chunk-lanes (contiguous, same warp;
    // total4 multiple of 256 -> no partial warps).
    __syncwarp();
    if (c == 0) g_deg[nodeIdx] = 0;
}

// ---------------------------------------------------------------------------
// Launch. Inputs: node_q(B,N,D) f32, node_p f32, observations(B,D) f32,
// kalman_gain(2D) f32, edges(E,2) i32.  D=64 fixed.
// ---------------------------------------------------------------------------
extern "C" void kernel_launch(void* const* d_in, const int* in_sizes, int n_in,
                              void* d_out, int out_size) {
    const float* q   = (const float*)d_in[0];
    const float* p   = (const float*)d_in[1];
    const float* obs = (const float*)d_in[2];
    const float* kg  = (const float*)d_in[3];
    const int*   edg = (const int*)  d_in[4];

    int D = in_sizes[3] / 2;                     // 64
    int B = in_sizes[2] / D;                     // 2
    int N = in_sizes[0] / (B * D);               // 20000
    int E = in_sizes[4] / 2;                     // 320000

    int totS = B * N * D;                        // 2,560,000
    int total4 = totS / 4;                       // 640000

    // 0) q -> fp16 copy (recomputed every launch; graph-replay safe)
    convert_kernel<<<(total4 + 255) / 256, 256>>>(q, total4);

    // 1) edge scatter (fp16 gathers + fp16 REDs)
    {
        long long t = (long long)E * 8;
        edge_kernel<<<(int)((t + 255) / 256), 256>>>(edg, E, N);
    }
    // 2) fused epilogue + scratch cleanup
    final_kernel<<<(total4 + 255) / 256, 256>>>(q, p, obs, kg,
                                                (float*)d_out, N, total4);
}